// round 8
// baseline (speedup 1.0000x reference)
#include <cuda_runtime.h>
#include <cuda_fp16.h>
#include <cstdint>

static __device__ __forceinline__ float ex2f(float x){
    float r; asm("ex2.approx.f32 %0, %1;" : "=f"(r) : "f"(x)); return r;
}
static __device__ __forceinline__ float rcpf(float x){
    float r; asm("rcp.approx.f32 %0, %1;" : "=f"(r) : "f"(x)); return r;
}
#define L2E 1.4426950408889634f

#define TT 8192
#define HH 128
#define II 16
#define PP 1024
#define NKK 9        // K = 144 = 9*16

// m16n8k16 fp16 MMA, fp32 accumulate.
static __device__ __forceinline__ void mma16816(
    float& d0, float& d1, float& d2, float& d3,
    uint32_t a0, uint32_t a1, uint32_t a2, uint32_t a3,
    uint32_t b0, uint32_t b1)
{
    asm("mma.sync.aligned.m16n8k16.row.col.f32.f16.f16.f32 "
        "{%0,%1,%2,%3}, {%4,%5,%6,%7}, {%8,%9}, {%0,%1,%2,%3};"
        : "+f"(d0), "+f"(d1), "+f"(d2), "+f"(d3)
        : "r"(a0), "r"(a1), "r"(a2), "r"(a3), "r"(b0), "r"(b1));
}

// W'(r,k): k<128 -> Whh[r][k], else Wih[r][k-128]; packs (k,k+1) to half2.
static __device__ __forceinline__ uint32_t pack_w(
    const float* __restrict__ Whh, const float* __restrict__ Wih, int r, int k)
{
    float2 f;
    if (k < HH) f = *reinterpret_cast<const float2*>(Whh + (size_t)r * HH + k);
    else        f = *reinterpret_cast<const float2*>(Wih + (size_t)r * II + (k - HH));
    __half2 h = __floats2half2_rn(f.x, f.y);
    return *reinterpret_cast<uint32_t*>(&h);
}

// vB layout (72 u32 per buffer), empirically validated in R7:
// k-iter kk, quad tq reads uint2 at index (4kk+tq)*2. Writer of pair j:
static __device__ __forceinline__ int vb_idx(int j){
    int kk = j >> 3, rem = j & 7;
    return (rem < 4) ? ((4*kk + rem)*2) : ((4*kk + rem - 4)*2 + 1);
}

// One CTA per batch. 512 threads, 16 warps. ROW-PERMUTED layout: warp w owns
// h-slots 8w..8w+7; permuted row p=32w+l maps to original gate row
// (l&3)*128 + 8w + (l>>2). All 4 gates of a slot live in one warp -> the
// entire cell update is intra-warp, leaving ONE __syncthreads per step.
__global__ void __launch_bounds__(512, 1)
lstm_mma2_kernel(const float* __restrict__ x,
                 const float* __restrict__ Wih,
                 const float* __restrict__ Whh,
                 const float* __restrict__ bih,
                 const float* __restrict__ bhh,
                 const float* __restrict__ Wfc,
                 const float* __restrict__ bfc,
                 float* __restrict__ out)
{
    __shared__ float xs[4][II];                       // fp32 x ring (dist-3 prefetch)
    __shared__ float hsh[2][HH];                      // fp32 h, double-buffered
    __shared__ __align__(16) uint32_t vB[2][72];      // fp16 [h;x] B, double-buffered
    __shared__ float sums_s[PP * 3];
    __shared__ float cnt_s[PP];

    const int tid = threadIdx.x;
    const int wid = tid >> 5;
    const int lid = tid & 31;
    const int b   = blockIdx.x;
    const int g   = lid >> 2;    // mma row group
    const int tq  = lid & 3;     // thread-in-quad

    // ---- resident A fragments over PERMUTED rows ----
    uint32_t aw[2][NKK][4];
    #pragma unroll
    for (int ti = 0; ti < 2; ti++){
        const int lpA = 16*ti + g;         // tile rows g and g+8
        const int lpB = 16*ti + g + 8;
        const int rA = (lpA & 3)*HH + 8*wid + (lpA >> 2);   // original gate rows
        const int rB = (lpB & 3)*HH + 8*wid + (lpB >> 2);
        #pragma unroll
        for (int kk = 0; kk < NKK; kk++){
            const int k0 = 16*kk + 2*tq;
            aw[ti][kk][0] = pack_w(Whh, Wih, rA, k0);
            aw[ti][kk][1] = pack_w(Whh, Wih, rB, k0);
            aw[ti][kk][2] = pack_w(Whh, Wih, rA, k0 + 8);
            aw[ti][kk][3] = pack_w(Whh, Wih, rB, k0 + 8);
        }
    }
    // my permuted row = 32*wid + lid; gate type = lid&3 (i,f,g,o)
    const int myrow = (lid & 3)*HH + 8*wid + (lid >> 2);
    const float bias = bih[myrow] + bhh[myrow];
    const bool  is_g = ((lid & 3) == 2);
    const float ka = is_g ? (-2.0f*L2E) : (-L2E);     // act = aa*rcp(1+ex2(ka*x))+bb
    const float aa = is_g ? 2.0f : 1.0f;
    const float ab = is_g ? -1.0f : 0.0f;

    // FC head: warp ch (0..2) owns output channel ch
    float wf0 = 0.f, wf1 = 0.f, wf2 = 0.f, wf3 = 0.f, bo = 0.f;
    if (wid < 3){
        wf0 = Wfc[wid*HH + lid];      wf1 = Wfc[wid*HH + 32 + lid];
        wf2 = Wfc[wid*HH + 64 + lid]; wf3 = Wfc[wid*HH + 96 + lid];
        bo  = bfc[wid];
    }

    // ---- init ----
    const float* xb = x + (size_t)b * TT * II;
    if (tid < 64) vB[0][tid] = 0u;                    // h(−1)=0
    if (tid < 8){                                     // x(0) into vB[0]
        __half2 xp = __floats2half2_rn(xb[2*tid], xb[2*tid + 1]);
        vB[0][(tid < 4) ? (32 + tid)*2 : (32 + tid - 4)*2 + 1]
            = *reinterpret_cast<uint32_t*>(&xp);
    }
    if (tid < 48) xs[tid >> 4][tid & 15] = xb[tid];   // x(0),x(1),x(2)
    for (int k = tid; k < PP;   k += 512) cnt_s[k]  = 0.f;
    for (int k = tid; k < 3*PP; k += 512) sums_s[k] = 0.f;
    __syncthreads();

    const uint32_t xs_base = (uint32_t)__cvta_generic_to_shared(&xs[0][0]);
    float c = 0.f;          // cell state for my slot (replicated across 4 lanes)
    float idf_prev = 0.f;   // id(t-1), used by FC

    #pragma unroll 2
    for (int t = 0; t < TT; t++){
        const int p = t & 1;

        // prefetch x(t+3) into ring slot (t+3)&3 (distance 3 ~= 2.8 intervals)
        if (tid < 4){
            int tn = t + 3; if (tn > TT - 1) tn = TT - 1;
            asm volatile("cp.async.ca.shared.global [%0], [%1], 16;\n\t"
                         "cp.async.commit_group;"
                         :: "r"(xs_base + (uint32_t)((((t+3)&3)*II + tid*4)*4)),
                            "l"(xb + (size_t)tn*II + tid*4) : "memory");
        }
        const float idf_cur = (wid < 3) ? xs[t & 3][2] : 0.f;

        // ---- MMA: two tiles x two kk-parity chains (depth <=5 each) ----
        float e0=0.f,e1=0.f,e2=0.f,e3=0.f, o0=0.f,o1=0.f,o2=0.f,o3=0.f;
        float f0=0.f,f1=0.f,f2=0.f,f3=0.f, q0=0.f,q1=0.f,q2=0.f,q3=0.f;
        #pragma unroll
        for (int kk = 0; kk < NKK; kk++){
            const uint2 bb = *reinterpret_cast<const uint2*>(&vB[p][(4*kk + tq)*2]);
            if (kk & 1){
                mma16816(o0,o1,o2,o3, aw[0][kk][0],aw[0][kk][1],aw[0][kk][2],aw[0][kk][3], bb.x, bb.y);
                mma16816(q0,q1,q2,q3, aw[1][kk][0],aw[1][kk][1],aw[1][kk][2],aw[1][kk][3], bb.x, bb.y);
            } else {
                mma16816(e0,e1,e2,e3, aw[0][kk][0],aw[0][kk][1],aw[0][kk][2],aw[0][kk][3], bb.x, bb.y);
                mma16816(f0,f1,f2,f3, aw[1][kk][0],aw[1][kk][1],aw[1][kk][2],aw[1][kk][3], bb.x, bb.y);
            }
        }
        const float t0c0 = e0 + o0, t0c2 = e2 + o2;   // tile0 rows g, g+8 (col 0)
        const float t1c0 = f0 + q0, t1c2 = f2 + q2;   // tile1

        // distribute: lane l <- gpre of permuted row 32w+l
        const int sl = (lid & 7) * 4;
        const float v0 = __shfl_sync(0xffffffffu, t0c0, sl);
        const float v1 = __shfl_sync(0xffffffffu, t0c2, sl);
        const float v2 = __shfl_sync(0xffffffffu, t1c0, sl);
        const float v3 = __shfl_sync(0xffffffffu, t1c2, sl);
        const int sel = lid >> 3;
        float gpre = ((sel == 0) ? v0 : (sel == 1) ? v1 : (sel == 2) ? v2 : v3) + bias;

        // unified activation (no divergence)
        const float av = fmaf(aa, rcpf(1.0f + ex2f(gpre * ka)), ab);

        // gather 4 gates of my slot (all intra-warp)
        const int base = lid & ~3;
        const float iv = __shfl_sync(0xffffffffu, av, base);
        const float fv = __shfl_sync(0xffffffffu, av, base + 1);
        const float gv = __shfl_sync(0xffffffffu, av, base + 2);
        const float ov = __shfl_sync(0xffffffffu, av, base + 3);
        c = fv * c + iv * gv;
        const float th = fmaf(2.0f, rcpf(1.0f + ex2f(c * (-2.0f*L2E))), -1.0f);
        const float hn = ov * th;

        // publish h(t): fp32 for FC, fp16 pairs for next MMA
        if ((lid & 3) == 0) hsh[p ^ 1][8*wid + (lid >> 2)] = hn;
        const float hn4 = __shfl_down_sync(0xffffffffu, hn, 4);
        if ((lid & 7) == 0){
            __half2 hp = __floats2half2_rn(hn, hn4);
            vB[p ^ 1][vb_idx(4*wid + (lid >> 3))] = *reinterpret_cast<uint32_t*>(&hp);
        }
        // x(t+1) -> fp16 B x-part (warp 15)
        if (wid == 15 && lid < 8 && t < TT - 1){
            const float* xsrc = xs[(t + 1) & 3];
            __half2 xp = __floats2half2_rn(xsrc[2*lid], xsrc[2*lid + 1]);
            vB[p ^ 1][(lid < 4) ? (32 + lid)*2 : (32 + lid - 4)*2 + 1]
                = *reinterpret_cast<uint32_t*>(&xp);
        }

        // FC head for h(t-1) + segment accumulate (off critical path)
        if (wid < 3 && t > 0){
            const float* hp = hsh[p];
            float v = hp[lid]*wf0 + hp[32+lid]*wf1 + hp[64+lid]*wf2 + hp[96+lid]*wf3;
            v += __shfl_xor_sync(0xffffffffu, v, 16);
            v += __shfl_xor_sync(0xffffffffu, v, 8);
            v += __shfl_xor_sync(0xffffffffu, v, 4);
            v += __shfl_xor_sync(0xffffffffu, v, 2);
            v += __shfl_xor_sync(0xffffffffu, v, 1);
            if (lid == 0){
                const int id = (int)idf_prev;
                if ((unsigned)id < (unsigned)PP){
                    sums_s[id*3 + wid] += v + bo;
                    if (wid == 0) cnt_s[id] += 1.f;
                }
            }
        }
        idf_prev = idf_cur;

        if (tid < 4) asm volatile("cp.async.wait_group 1;" ::: "memory");
        __syncthreads();   // the ONE barrier per step
    }

    // ---- final FC for h(T-1) (in hsh[0]) with id(T-1) ----
    if (wid < 3){
        const float* hp = hsh[0];
        float v = hp[lid]*wf0 + hp[32+lid]*wf1 + hp[64+lid]*wf2 + hp[96+lid]*wf3;
        v += __shfl_xor_sync(0xffffffffu, v, 16);
        v += __shfl_xor_sync(0xffffffffu, v, 8);
        v += __shfl_xor_sync(0xffffffffu, v, 4);
        v += __shfl_xor_sync(0xffffffffu, v, 2);
        v += __shfl_xor_sync(0xffffffffu, v, 1);
        if (lid == 0){
            const int id = (int)idf_prev;
            if ((unsigned)id < (unsigned)PP){
                sums_s[id*3 + wid] += v + bo;
                if (wid == 0) cnt_s[id] += 1.f;
            }
        }
    }
    __syncthreads();

    // ---- epilogue: mean per (batch, photo) ----
    for (int k = tid; k < 3*PP; k += 512){
        float cn = cnt_s[k / 3];
        if (cn == 0.f) cn = 1.f;
        out[(size_t)b * 3 * PP + k] = sums_s[k] / cn;
    }
}

extern "C" void kernel_launch(void* const* d_in, const int* in_sizes, int n_in,
                              void* d_out, int out_size)
{
    const float *x = 0, *Wih = 0, *Whh = 0, *b1 = 0, *b2 = 0, *Wfc = 0, *bfc = 0;
    for (int i = 0; i < n_in; i++){
        const float* p = (const float*)d_in[i];
        switch (in_sizes[i]){
            case 32*8192*16: x   = p; break;
            case 512*16:     Wih = p; break;
            case 512*128:    Whh = p; break;
            case 512:        if (!b1) b1 = p; else b2 = p; break;
            case 3*128:      Wfc = p; break;
            case 3:          bfc = p; break;
            default: break;
        }
    }
    if (!x)   x   = (const float*)d_in[0];
    if (!Wih) Wih = (const float*)d_in[1];
    if (!Whh) Whh = (const float*)d_in[2];
    if (!b1)  b1  = (const float*)d_in[3];
    if (!b2)  b2  = (const float*)d_in[4];
    if (!Wfc) Wfc = (const float*)d_in[5];
    if (!bfc) bfc = (const float*)d_in[6];

    float* out = (float*)d_out;
    lstm_mma2_kernel<<<32, 512>>>(x, Wih, Whh, b1, b2, Wfc, bfc, out);
}

// round 9
// speedup vs baseline: 1.0005x; 1.0005x over previous
#include <cuda_runtime.h>
#include <cuda_fp16.h>
#include <cstdint>

static __device__ __forceinline__ float ex2f(float x){
    float r; asm("ex2.approx.f32 %0, %1;" : "=f"(r) : "f"(x)); return r;
}
static __device__ __forceinline__ float rcpf(float x){
    float r; asm("rcp.approx.f32 %0, %1;" : "=f"(r) : "f"(x)); return r;
}
#define L2E 1.4426950408889634f

#define TT 8192
#define HH 128
#define II 16
#define PP 1024
#define NKK 8        // K = 128 (h only; x handled scalar, off critical path)

// m16n8k16 fp16 MMA, fp32 accumulate.
static __device__ __forceinline__ void mma16816(
    float& d0, float& d1, float& d2, float& d3,
    uint32_t a0, uint32_t a1, uint32_t a2, uint32_t a3,
    uint32_t b0, uint32_t b1)
{
    asm("mma.sync.aligned.m16n8k16.row.col.f32.f16.f16.f32 "
        "{%0,%1,%2,%3}, {%4,%5,%6,%7}, {%8,%9}, {%0,%1,%2,%3};"
        : "+f"(d0), "+f"(d1), "+f"(d2), "+f"(d3)
        : "r"(a0), "r"(a1), "r"(a2), "r"(a3), "r"(b0), "r"(b1));
}

static __device__ __forceinline__ uint32_t pack_whh(
    const float* __restrict__ Whh, int r, int k)
{
    float2 f = *reinterpret_cast<const float2*>(Whh + (size_t)r * HH + k);
    __half2 h = __floats2half2_rn(f.x, f.y);
    return *reinterpret_cast<uint32_t*>(&h);
}

// vB layout (64 u32 per buffer): k-iter kk, quad tq reads uint2 at (4kk+tq)*2.
// Writer of h-pair j (j in 0..63):
static __device__ __forceinline__ int vb_idx(int j){
    int kk = j >> 3, rem = j & 7;
    return (rem < 4) ? ((4*kk + rem)*2) : ((4*kk + rem - 4)*2 + 1);
}

// One CTA per batch, 512 threads, 16 warps. Row-permuted layout (validated in
// R8): warp w owns h-slots 8w..8w+7; permuted row 32w+l = original gate row
// (l&3)*128 + 8w + (l>>2). All 4 gates of a slot are intra-warp -> one
// __syncthreads per step. W_hh resident as fp16 A-fragments (64 u32/thread);
// W_ih resident as 8 half2; x contribution precomputed one step ahead.
__global__ void __launch_bounds__(512, 1)
lstm_mma3_kernel(const float* __restrict__ x,
                 const float* __restrict__ Wih,
                 const float* __restrict__ Whh,
                 const float* __restrict__ bih,
                 const float* __restrict__ bhh,
                 const float* __restrict__ Wfc,
                 const float* __restrict__ bfc,
                 float* __restrict__ out)
{
    __shared__ float xs[4][II];                       // fp32 x ring (dist-2 prefetch)
    __shared__ float hsh[2][HH];                      // fp32 h, double-buffered
    __shared__ __align__(16) uint32_t vB[2][64];      // fp16 h B-operand, double-buffered
    __shared__ float sums_s[PP * 3];
    __shared__ float cnt_s[PP];

    const int tid = threadIdx.x;
    const int wid = tid >> 5;
    const int lid = tid & 31;
    const int b   = blockIdx.x;
    const int g   = lid >> 2;
    const int tq  = lid & 3;

    // ---- resident A fragments (W_hh only, K=128) over permuted rows ----
    uint32_t aw[2][NKK][4];
    #pragma unroll
    for (int ti = 0; ti < 2; ti++){
        const int lpA = 16*ti + g;
        const int lpB = 16*ti + g + 8;
        const int rA = (lpA & 3)*HH + 8*wid + (lpA >> 2);
        const int rB = (lpB & 3)*HH + 8*wid + (lpB >> 2);
        #pragma unroll
        for (int kk = 0; kk < NKK; kk++){
            const int k0 = 16*kk + 2*tq;
            aw[ti][kk][0] = pack_whh(Whh, rA, k0);
            aw[ti][kk][1] = pack_whh(Whh, rB, k0);
            aw[ti][kk][2] = pack_whh(Whh, rA, k0 + 8);
            aw[ti][kk][3] = pack_whh(Whh, rB, k0 + 8);
        }
    }
    // my permuted row; gate type = lid&3 (i,f,g,o)
    const int myrow = (lid & 3)*HH + 8*wid + (lid >> 2);
    const float bias = bih[myrow] + bhh[myrow];
    const bool  is_g = ((lid & 3) == 2);
    const float ka = is_g ? (-2.0f*L2E) : (-L2E);
    const float aa = is_g ? 2.0f : 1.0f;
    const float ab = is_g ? -1.0f : 0.0f;

    // resident W_ih row as 8 half2
    uint32_t wihp[8];
    #pragma unroll
    for (int i = 0; i < 8; i++){
        float2 f = *reinterpret_cast<const float2*>(Wih + (size_t)myrow * II + 2*i);
        __half2 h = __floats2half2_rn(f.x, f.y);
        wihp[i] = *reinterpret_cast<uint32_t*>(&h);
    }

    // FC head: warp ch (0..2) owns output channel ch
    float wf0 = 0.f, wf1 = 0.f, wf2 = 0.f, wf3 = 0.f, bo = 0.f;
    if (wid < 3){
        wf0 = Wfc[wid*HH + lid];      wf1 = Wfc[wid*HH + 32 + lid];
        wf2 = Wfc[wid*HH + 64 + lid]; wf3 = Wfc[wid*HH + 96 + lid];
        bo  = bfc[wid];
    }

    // ---- init ----
    const float* xb = x + (size_t)b * TT * II;
    if (tid < 64) vB[0][tid] = 0u;                    // h(-1) = 0
    if (tid < 64) xs[tid >> 4][tid & 15] = xb[tid];   // x(0..3)
    for (int k = tid; k < PP;   k += 512) cnt_s[k]  = 0.f;
    for (int k = tid; k < 3*PP; k += 512) sums_s[k] = 0.f;
    __syncthreads();

    // xcon for step 0 (x(0)): two partial chains of 4 FMAs each
    float xcon;
    {
        const float* xp = xs[0];
        float aA = 0.f, aB = 0.f;
        #pragma unroll
        for (int i = 0; i < 4; i++){
            float2 wA = __half22float2(*reinterpret_cast<const __half2*>(&wihp[i]));
            float2 wB = __half22float2(*reinterpret_cast<const __half2*>(&wihp[i+4]));
            aA += wA.x*xp[2*i]   + wA.y*xp[2*i+1];
            aB += wB.x*xp[2*i+8] + wB.y*xp[2*i+9];
        }
        xcon = aA + aB;
    }

    float c = 0.f;          // cell state for my slot (replicated across the quad)
    float idf_prev = 0.f;

    #pragma unroll 1
    for (int t = 0; t < TT; t++){
        const int p = t & 1;

        // prefetch x(t+2) into register (stored to ring before the barrier)
        float xr = 0.f;
        if (tid < II){
            int tn = t + 2; if (tn > TT - 1) tn = TT - 1;
            xr = __ldg(xb + (size_t)tn * II + tid);
        }

        // ---- MMA: 2 tiles x 2 kk-parity chains (dependent depth 4) ----
        float e0=0.f,e1=0.f,e2=0.f,e3=0.f, o0=0.f,o1=0.f,o2=0.f,o3=0.f;
        float f0=0.f,f1=0.f,f2=0.f,f3=0.f, q0=0.f,q1=0.f,q2=0.f,q3=0.f;
        #pragma unroll
        for (int kk = 0; kk < NKK; kk++){
            const uint2 bb = *reinterpret_cast<const uint2*>(&vB[p][(4*kk + tq)*2]);
            if (kk & 1){
                mma16816(o0,o1,o2,o3, aw[0][kk][0],aw[0][kk][1],aw[0][kk][2],aw[0][kk][3], bb.x, bb.y);
                mma16816(q0,q1,q2,q3, aw[1][kk][0],aw[1][kk][1],aw[1][kk][2],aw[1][kk][3], bb.x, bb.y);
            } else {
                mma16816(e0,e1,e2,e3, aw[0][kk][0],aw[0][kk][1],aw[0][kk][2],aw[0][kk][3], bb.x, bb.y);
                mma16816(f0,f1,f2,f3, aw[1][kk][0],aw[1][kk][1],aw[1][kk][2],aw[1][kk][3], bb.x, bb.y);
            }
        }
        const float t0c0 = e0 + o0, t0c2 = e2 + o2;
        const float t1c0 = f0 + q0, t1c2 = f2 + q2;

        // distribute: lane l <- gpre of permuted row 32w+l  (validated in R8)
        const int sl = (lid & 7) * 4;
        const float v0 = __shfl_sync(0xffffffffu, t0c0, sl);
        const float v1 = __shfl_sync(0xffffffffu, t0c2, sl);
        const float v2 = __shfl_sync(0xffffffffu, t1c0, sl);
        const float v3 = __shfl_sync(0xffffffffu, t1c2, sl);
        const int sel = lid >> 3;
        const float gpre = ((sel == 0) ? v0 : (sel == 1) ? v1 : (sel == 2) ? v2 : v3)
                           + bias + xcon;

        // unified activation (no divergent paths)
        const float av = fmaf(aa, rcpf(1.0f + ex2f(gpre * ka)), ab);

        // gather the 4 gates of my slot (within the quad)
        const int base = lid & ~3;
        const float iv = __shfl_sync(0xffffffffu, av, base);
        const float fv = __shfl_sync(0xffffffffu, av, base + 1);
        const float gv = __shfl_sync(0xffffffffu, av, base + 2);
        const float ov = __shfl_sync(0xffffffffu, av, base + 3);
        c = fv * c + iv * gv;
        const float th = fmaf(2.0f, rcpf(1.0f + ex2f(c * (-2.0f*L2E))), -1.0f);
        const float hn = ov * th;

        // publish h(t): fp32 for the FC head, fp16 pairs for next step's MMA
        if ((lid & 3) == 0) hsh[p ^ 1][8*wid + (lid >> 2)] = hn;
        const float hn4 = __shfl_down_sync(0xffffffffu, hn, 4);
        if ((lid & 7) == 0){
            __half2 hp = __floats2half2_rn(hn, hn4);
            vB[p ^ 1][vb_idx(4*wid + (lid >> 3))] = *reinterpret_cast<uint32_t*>(&hp);
        }

        // FC head for h(t-1) + segment accumulate (warps 0..2)
        if (wid < 3 && t > 0){
            const float* hp = hsh[p];
            float v = hp[lid]*wf0 + hp[32+lid]*wf1 + hp[64+lid]*wf2 + hp[96+lid]*wf3;
            v += __shfl_xor_sync(0xffffffffu, v, 16);
            v += __shfl_xor_sync(0xffffffffu, v, 8);
            v += __shfl_xor_sync(0xffffffffu, v, 4);
            v += __shfl_xor_sync(0xffffffffu, v, 2);
            v += __shfl_xor_sync(0xffffffffu, v, 1);
            if (lid == 0){
                const int id = (int)idf_prev;
                if ((unsigned)id < (unsigned)PP){
                    sums_s[id*3 + wid] += v + bo;
                    if (wid == 0) cnt_s[id] += 1.f;
                }
            }
        }
        idf_prev = xs[t & 3][2];          // id(t), consumed by FC next step

        // xcon for step t+1 (x(t+1)); off the critical chain
        {
            const float* xp = xs[(t + 1) & 3];
            float aA = 0.f, aB = 0.f;
            #pragma unroll
            for (int i = 0; i < 4; i++){
                float2 wA = __half22float2(*reinterpret_cast<const __half2*>(&wihp[i]));
                float2 wB = __half22float2(*reinterpret_cast<const __half2*>(&wihp[i+4]));
                aA += wA.x*xp[2*i]   + wA.y*xp[2*i+1];
                aB += wB.x*xp[2*i+8] + wB.y*xp[2*i+9];
            }
            xcon = aA + aB;
        }

        if (tid < II) xs[(t + 2) & 3][tid] = xr;   // slot's old x(t-2) is long dead

        __syncthreads();   // the ONE barrier per step
    }

    // ---- final FC for h(T-1) (in hsh[0]) with id(T-1) ----
    if (wid < 3){
        const float* hp = hsh[0];
        float v = hp[lid]*wf0 + hp[32+lid]*wf1 + hp[64+lid]*wf2 + hp[96+lid]*wf3;
        v += __shfl_xor_sync(0xffffffffu, v, 16);
        v += __shfl_xor_sync(0xffffffffu, v, 8);
        v += __shfl_xor_sync(0xffffffffu, v, 4);
        v += __shfl_xor_sync(0xffffffffu, v, 2);
        v += __shfl_xor_sync(0xffffffffu, v, 1);
        if (lid == 0){
            const int id = (int)idf_prev;
            if ((unsigned)id < (unsigned)PP){
                sums_s[id*3 + wid] += v + bo;
                if (wid == 0) cnt_s[id] += 1.f;
            }
        }
    }
    __syncthreads();

    // ---- epilogue: mean per (batch, photo) ----
    for (int k = tid; k < 3*PP; k += 512){
        float cn = cnt_s[k / 3];
        if (cn == 0.f) cn = 1.f;
        out[(size_t)b * 3 * PP + k] = sums_s[k] / cn;
    }
}

extern "C" void kernel_launch(void* const* d_in, const int* in_sizes, int n_in,
                              void* d_out, int out_size)
{
    const float *x = 0, *Wih = 0, *Whh = 0, *b1 = 0, *b2 = 0, *Wfc = 0, *bfc = 0;
    for (int i = 0; i < n_in; i++){
        const float* p = (const float*)d_in[i];
        switch (in_sizes[i]){
            case 32*8192*16: x   = p; break;
            case 512*16:     Wih = p; break;
            case 512*128:    Whh = p; break;
            case 512:        if (!b1) b1 = p; else b2 = p; break;
            case 3*128:      Wfc = p; break;
            case 3:          bfc = p; break;
            default: break;
        }
    }
    if (!x)   x   = (const float*)d_in[0];
    if (!Wih) Wih = (const float*)d_in[1];
    if (!Whh) Whh = (const float*)d_in[2];
    if (!b1)  b1  = (const float*)d_in[3];
    if (!b2)  b2  = (const float*)d_in[4];
    if (!Wfc) Wfc = (const float*)d_in[5];
    if (!bfc) bfc = (const float*)d_in[6];

    float* out = (float*)d_out;
    lstm_mma3_kernel<<<32, 512>>>(x, Wih, Whh, b1, b2, Wfc, bfc, out);
}

// round 10
// speedup vs baseline: 1.2020x; 1.2014x over previous
#include <cuda_runtime.h>
#include <cuda_fp16.h>
#include <cstdint>

static __device__ __forceinline__ float ex2f(float x){
    float r; asm("ex2.approx.f32 %0, %1;" : "=f"(r) : "f"(x)); return r;
}
static __device__ __forceinline__ float rcpf(float x){
    float r; asm("rcp.approx.f32 %0, %1;" : "=f"(r) : "f"(x)); return r;
}
#define L2E 1.4426950408889634f
static __device__ __forceinline__ float sigmoid_acc(float x){
    return rcpf(1.0f + ex2f(-x * L2E));
}
static __device__ __forceinline__ float tanh_acc(float x){
    return 1.0f - 2.0f * rcpf(ex2f(2.0f * L2E * x) + 1.0f);
}

#define TT 8192
#define HH 128
#define II 16
#define PP 1024
#define NKK 8        // K = 128 (W_hh only; x contribution is scalar, off-path)

// m16n8k16 fp16 MMA, fp32 accumulate.
static __device__ __forceinline__ void mma16816(
    float& d0, float& d1, float& d2, float& d3,
    uint32_t a0, uint32_t a1, uint32_t a2, uint32_t a3,
    uint32_t b0, uint32_t b1)
{
    asm("mma.sync.aligned.m16n8k16.row.col.f32.f16.f16.f32 "
        "{%0,%1,%2,%3}, {%4,%5,%6,%7}, {%8,%9}, {%0,%1,%2,%3};"
        : "+f"(d0), "+f"(d1), "+f"(d2), "+f"(d3)
        : "r"(a0), "r"(a1), "r"(a2), "r"(a3), "r"(b0), "r"(b1));
}

static __device__ __forceinline__ uint32_t pack_whh(
    const float* __restrict__ Whh, int r, int k)
{
    float2 f = *reinterpret_cast<const float2*>(Whh + (size_t)r * HH + k);
    __half2 h = __floats2half2_rn(f.x, f.y);
    return *reinterpret_cast<uint32_t*>(&h);
}

// vB layout (64 u32): k-iter kk, quad tq reads uint2 at (4kk+tq)*2.
// Writer of h-pair j: (validated in R7)
static __device__ __forceinline__ int vb_idx(int j){
    int kk = j >> 3, rem = j & 7;
    return (rem < 4) ? ((4*kk + rem)*2) : ((4*kk + rem - 4)*2 + 1);
}

// R7 skeleton: one CTA per batch, 512 threads, warp w owns gate rows
// 32w..32w+31 (gate type = w>>2, order i,f,g,o), act exchanged through SMEM
// with two barriers. W_hh resident as fp16 A-fragments (64 u32/thread),
// W_ih resident as 8 half2; parity-split accumulators (HMMA chain depth 4).
__global__ void __launch_bounds__(512, 1)
lstm_mma4_kernel(const float* __restrict__ x,
                 const float* __restrict__ Wih,
                 const float* __restrict__ Whh,
                 const float* __restrict__ bih,
                 const float* __restrict__ bhh,
                 const float* __restrict__ Wfc,
                 const float* __restrict__ bfc,
                 float* __restrict__ out)
{
    __shared__ float xsh[2][II];                       // fp32 x double buffer
    __shared__ float hsh[HH];                          // fp32 h (for FC head)
    __shared__ float act[512];                         // activated gates
    __shared__ __align__(16) uint32_t vB[64];          // fp16 h B-operand
    __shared__ float sums_s[PP * 3];
    __shared__ float cnt_s[PP];

    const int tid = threadIdx.x;
    const int wid = tid >> 5;
    const int lid = tid & 31;
    const int b   = blockIdx.x;
    const int g   = lid >> 2;    // mma row group
    const int tq  = lid & 3;     // thread-in-quad

    // ---- resident A fragments (W_hh only, K=128) ----
    uint32_t aw[2][NKK][4];
    #pragma unroll
    for (int ti = 0; ti < 2; ti++){
        const int r0 = 32*wid + 16*ti + g;
        #pragma unroll
        for (int kk = 0; kk < NKK; kk++){
            const int k0 = 16*kk + 2*tq;
            aw[ti][kk][0] = pack_whh(Whh, r0,     k0);
            aw[ti][kk][1] = pack_whh(Whh, r0 + 8, k0);
            aw[ti][kk][2] = pack_whh(Whh, r0,     k0 + 8);
            aw[ti][kk][3] = pack_whh(Whh, r0 + 8, k0 + 8);
        }
    }
    const float bias = bih[tid] + bhh[tid];
    const bool  is_tanh_gate = ((tid >> 7) == 2);

    // resident W_ih row as 8 half2 (for the scalar x contribution)
    uint32_t wihp[8];
    #pragma unroll
    for (int i = 0; i < 8; i++){
        float2 f = *reinterpret_cast<const float2*>(Wih + (size_t)tid * II + 2*i);
        __half2 h = __floats2half2_rn(f.x, f.y);
        wihp[i] = *reinterpret_cast<uint32_t*>(&h);
    }

    // FC head: warp ch (0..2) owns output channel ch
    float wf0 = 0.f, wf1 = 0.f, wf2 = 0.f, wf3 = 0.f, bo = 0.f;
    if (wid < 3){
        wf0 = Wfc[wid*HH + lid];      wf1 = Wfc[wid*HH + 32 + lid];
        wf2 = Wfc[wid*HH + 64 + lid]; wf3 = Wfc[wid*HH + 96 + lid];
        bo  = bfc[wid];
    }

    // ---- init shared state ----
    const float* xb = x + (size_t)b * TT * II;
    if (tid < 64) vB[tid] = 0u;                       // h(-1) = 0
    if (tid < II){ xsh[0][tid] = xb[tid]; xsh[1][tid] = xb[II + tid]; }
    for (int k = tid; k < PP;   k += 512) cnt_s[k]  = 0.f;
    for (int k = tid; k < 3*PP; k += 512) sums_s[k] = 0.f;
    __syncthreads();

    // xcon for step 0: wih[tid,:] . x(0), two partial chains
    float xcon;
    {
        const float* xp = xsh[0];
        float aA = 0.f, aB = 0.f;
        #pragma unroll
        for (int i = 0; i < 4; i++){
            float2 wA = __half22float2(*reinterpret_cast<const __half2*>(&wihp[i]));
            float2 wB = __half22float2(*reinterpret_cast<const __half2*>(&wihp[i+4]));
            aA += wA.x*xp[2*i]   + wA.y*xp[2*i+1];
            aB += wB.x*xp[2*i+8] + wB.y*xp[2*i+9];
        }
        xcon = aA + aB;
    }

    float c = 0.f;   // cell state (threads 0..127)

    for (int t = 0; t < TT; t++){
        // ================= S1: MMA GEMV + activations =================
        const float idf = xsh[t & 1][2];               // photo id of step t
        float xr = 0.f;
        if (tid < II){                                 // prefetch x(t+2)
            int tn = t + 2; if (tn > TT - 1) tn = TT - 1;
            xr = __ldg(xb + (size_t)tn * II + tid);
        }

        // 2 tiles x 2 kk-parity chains -> dependent HMMA depth 4
        float e0=0.f,e1=0.f,e2=0.f,e3=0.f, o0=0.f,o1=0.f,o2=0.f,o3=0.f;
        float f0=0.f,f1=0.f,f2=0.f,f3=0.f, q0=0.f,q1=0.f,q2=0.f,q3=0.f;
        #pragma unroll
        for (int kk = 0; kk < NKK; kk++){
            const uint2 bb = *reinterpret_cast<const uint2*>(&vB[(4*kk + tq)*2]);
            if (kk & 1){
                mma16816(o0,o1,o2,o3, aw[0][kk][0],aw[0][kk][1],aw[0][kk][2],aw[0][kk][3], bb.x, bb.y);
                mma16816(q0,q1,q2,q3, aw[1][kk][0],aw[1][kk][1],aw[1][kk][2],aw[1][kk][3], bb.x, bb.y);
            } else {
                mma16816(e0,e1,e2,e3, aw[0][kk][0],aw[0][kk][1],aw[0][kk][2],aw[0][kk][3], bb.x, bb.y);
                mma16816(f0,f1,f2,f3, aw[1][kk][0],aw[1][kk][1],aw[1][kk][2],aw[1][kk][3], bb.x, bb.y);
            }
        }
        const float t0c0 = e0 + o0, t0c2 = e2 + o2;   // tile0 rows g, g+8 (col 0)
        const float t1c0 = f0 + q0, t1c2 = f2 + q2;   // tile1

        // distribute col-0 results: row (32w+l) ends up in lane l (validated R7)
        const int sl = (lid & 7) * 4;
        const float v0 = __shfl_sync(0xffffffffu, t0c0, sl);
        const float v1 = __shfl_sync(0xffffffffu, t0c2, sl);
        const float v2 = __shfl_sync(0xffffffffu, t1c0, sl);
        const float v3 = __shfl_sync(0xffffffffu, t1c2, sl);
        const int sel = lid >> 3;
        const float gpre = ((sel == 0) ? v0 : (sel == 1) ? v1 : (sel == 2) ? v2 : v3)
                           + bias + xcon;
        act[tid] = is_tanh_gate ? tanh_acc(gpre) : sigmoid_acc(gpre);
        __syncthreads();   // A

        // ============ S2: cell/hidden update + fp16 B refresh ============
        if (tid < HH){
            const float iv = act[tid];
            const float fv = act[HH + tid];
            const float gv = act[2*HH + tid];
            const float ov = act[3*HH + tid];
            c = fv * c + iv * gv;
            const float hn = ov * tanh_acc(c);
            hsh[tid] = hn;
            const float hn1 = __shfl_down_sync(0xffffffffu, hn, 1);
            if (!(tid & 1)){
                __half2 hp = __floats2half2_rn(hn, hn1);
                vB[vb_idx(tid >> 1)] = *reinterpret_cast<uint32_t*>(&hp);
            }
        }
        __syncthreads();   // B

        // ============ S3: FC head + segment accumulate + x/xcon refresh ======
        if (wid < 3){
            float v = hsh[lid]      * wf0 + hsh[32 + lid] * wf1
                    + hsh[64 + lid] * wf2 + hsh[96 + lid] * wf3;
            v += __shfl_xor_sync(0xffffffffu, v, 16);
            v += __shfl_xor_sync(0xffffffffu, v, 8);
            v += __shfl_xor_sync(0xffffffffu, v, 4);
            v += __shfl_xor_sync(0xffffffffu, v, 2);
            v += __shfl_xor_sync(0xffffffffu, v, 1);
            if (lid == 0){
                const int id = (int)idf;
                if ((unsigned)id < (unsigned)PP){
                    sums_s[id*3 + wid] += v + bo;
                    if (wid == 0) cnt_s[id] += 1.f;
                }
            }
        }
        // xcon for step t+1 (x(t+1) lives in xsh[(t+1)&1] all of step t)
        {
            const float* xp = xsh[(t + 1) & 1];
            float aA = 0.f, aB = 0.f;
            #pragma unroll
            for (int i = 0; i < 4; i++){
                float2 wA = __half22float2(*reinterpret_cast<const __half2*>(&wihp[i]));
                float2 wB = __half22float2(*reinterpret_cast<const __half2*>(&wihp[i+4]));
                aA += wA.x*xp[2*i]   + wA.y*xp[2*i+1];
                aB += wB.x*xp[2*i+8] + wB.y*xp[2*i+9];
            }
            xcon = aA + aB;
        }
        if (tid < II) xsh[t & 1][tid] = xr;            // x(t+2) into retired buffer
    }

    // ---- epilogue: mean per (batch, photo) ----
    __syncthreads();
    for (int k = tid; k < 3*PP; k += 512){
        float cn = cnt_s[k / 3];
        if (cn == 0.f) cn = 1.f;
        out[(size_t)b * 3 * PP + k] = sums_s[k] / cn;
    }
}

extern "C" void kernel_launch(void* const* d_in, const int* in_sizes, int n_in,
                              void* d_out, int out_size)
{
    const float *x = 0, *Wih = 0, *Whh = 0, *b1 = 0, *b2 = 0, *Wfc = 0, *bfc = 0;
    for (int i = 0; i < n_in; i++){
        const float* p = (const float*)d_in[i];
        switch (in_sizes[i]){
            case 32*8192*16: x   = p; break;
            case 512*16:     Wih = p; break;
            case 512*128:    Whh = p; break;
            case 512:        if (!b1) b1 = p; else b2 = p; break;
            case 3*128:      Wfc = p; break;
            case 3:          bfc = p; break;
            default: break;
        }
    }
    if (!x)   x   = (const float*)d_in[0];
    if (!Wih) Wih = (const float*)d_in[1];
    if (!Whh) Whh = (const float*)d_in[2];
    if (!b1)  b1  = (const float*)d_in[3];
    if (!b2)  b2  = (const float*)d_in[4];
    if (!Wfc) Wfc = (const float*)d_in[5];
    if (!bfc) bfc = (const float*)d_in[6];

    float* out = (float*)d_out;
    lstm_mma4_kernel<<<32, 512>>>(x, Wih, Whh, b1, b2, Wfc, bfc, out);
}